// round 9
// baseline (speedup 1.0000x reference)
#include <cuda_runtime.h>

#define NB    4
#define P1N   8192
#define P2N   8192
#define KK    16
#define TILE  2048
#define BLOCK 256

// BIT-EXACT vs reference (proven R8): XLA small-row shuffle reduce:
// sq = (x^2 + z^2) + y^2, each square individually rounded.
__device__ __forceinline__ float sumsq3(float x, float y, float z) {
    return __fadd_rn(__fadd_rn(__fmul_rn(x, x), __fmul_rn(z, z)),
                     __fmul_rn(y, y));
}

__global__ __launch_bounds__(BLOCK) void knn_topk_kernel(
    const float* __restrict__ p1,
    const float* __restrict__ p2,
    float* __restrict__ out)
{
    __shared__ float4 sm[TILE];

    const int blocks_per_batch = P1N / BLOCK;          // 32
    const int n = blockIdx.x / blocks_per_batch;       // batch
    const int q = (blockIdx.x % blocks_per_batch) * BLOCK + threadIdx.x;

    const float* p1r = p1 + ((size_t)n * P1N + q) * 3;
    const float x1 = p1r[0];
    const float y1 = p1r[1];
    const float z1 = p1r[2];
    const float sq1 = sumsq3(x1, y1, z1);

    // top-K as DESCENDING sorted list: dq[0] = worst (max), dq[15] = best
    float dq[KK];
    int   iq[KK];
    const float INF = __int_as_float(0x7f800000);
#pragma unroll
    for (int i = 0; i < KK; i++) { dq[i] = INF; iq[i] = 0; }

    const float* p2b = p2 + (size_t)n * P2N * 3;

    for (int t = 0; t < P2N; t += TILE) {
        __syncthreads();
        for (int i = threadIdx.x; i < TILE; i += BLOCK) {
            const float* pr = p2b + (size_t)(t + i) * 3;
            float x = pr[0], y = pr[1], z = pr[2];
            sm[i] = make_float4(x, y, z, sumsq3(x, y, z));
        }
        __syncthreads();

        float worst = dq[0];
#pragma unroll 4
        for (int jj = 0; jj < TILE; jj++) {
            float4 s = sm[jj];
            // inner: cuBLAS FFMA sgemm asc-k chain (bit-exact, proven R8)
            float inr = __fmaf_rn(z1, s.z,
                         __fmaf_rn(y1, s.y,
                          __fmul_rn(x1, s.x)));
            float S = __fadd_rn(sq1, s.w);
            // fma(-2,I,S) == fsub(S, 2*I) bit-exactly (2*I exact, one rounding)
            float d = __fmaf_rn(-2.0f, inr, S);

            bool mine = d < worst;
            // uniform branch: no BSSY/BSYNC divergence sync on the hot path
            if (__any_sync(0xffffffffu, mine)) {
                int j = t + jj;
                // identity ladder for lanes with !mine (all p_i false too)
                bool pprev = mine;
#pragma unroll
                for (int i = 0; i < KK - 1; i++) {
                    bool pi = d < dq[i + 1];
                    // value: shift, or min(d, dq[i]) (= d iff pprev)
                    float nd = pi ? dq[i + 1] : fminf(d, dq[i]);
                    int   ni = pi ? iq[i + 1] : (pprev ? j : iq[i]);
                    dq[i] = nd;
                    iq[i] = ni;
                    pprev = pi;
                }
                dq[KK - 1] = fminf(d, dq[KK - 1]);
                iq[KK - 1] = pprev ? j : iq[KK - 1];
                worst = dq[0];
            }
        }
    }

    // Output: concat(idxs (N,P1,K) as float32, dists (N,P1,K)), ascending rows.
    const size_t base = ((size_t)n * P1N + q) * KK;
    const size_t NPK  = (size_t)NB * P1N * KK;
#pragma unroll
    for (int k = 0; k < KK; k++) {
        out[base + k]       = (float)iq[KK - 1 - k];
        out[NPK + base + k] = dq[KK - 1 - k];
    }
}

extern "C" void kernel_launch(void* const* d_in, const int* in_sizes, int n_in,
                              void* d_out, int out_size)
{
    const float* p1 = (const float*)d_in[0];
    const float* p2 = (const float*)d_in[1];
    float* out = (float*)d_out;

    dim3 grid(NB * (P1N / BLOCK));  // 128 blocks
    dim3 block(BLOCK);
    knn_topk_kernel<<<grid, block>>>(p1, p2, out);
}

// round 10
// speedup vs baseline: 1.6637x; 1.6637x over previous
#include <cuda_runtime.h>

#define NB     4
#define P1N    8192
#define P2N    8192
#define KK     16
#define TILE   1024
#define CHUNK  128
#define BLOCK  224
#define BPB    37          // blocks per batch: 37*224 = 8288 >= 8192
#define CAP    24          // per-thread buffer capacity (items)
#define SLOTS  25          // CAP + 1 dummy slot
#define SMEM_BYTES (TILE * 16 + BLOCK * SLOTS * 8)

// BIT-EXACT (proven R8): XLA small-row shuffle reduce (x^2+z^2)+y^2
__device__ __forceinline__ float sumsq3(float x, float y, float z) {
    return __fadd_rn(__fadd_rn(__fmul_rn(x, x), __fmul_rn(z, z)),
                     __fmul_rn(y, y));
}

// Exact insert into descending top-K list. If d == +INF -> provable identity.
// If d >= dq[0] -> provable identity (reject). Ties: lower index wins
// (strict '<', insertion order = index order).
__device__ __forceinline__ void ladder(float d, int j,
                                       float (&dq)[KK], int (&iq)[KK]) {
    bool pprev = d < dq[0];
#pragma unroll
    for (int i = 0; i < KK - 1; i++) {
        bool pi = d < dq[i + 1];
        float nd = pi ? dq[i + 1] : fminf(d, dq[i]);
        int   ni = pi ? iq[i + 1] : (pprev ? j : iq[i]);
        dq[i] = nd;
        iq[i] = ni;
        pprev = pi;
    }
    dq[KK - 1] = fminf(d, dq[KK - 1]);
    iq[KK - 1] = pprev ? j : iq[KK - 1];
}

__global__ __launch_bounds__(BLOCK, 1) void knn_topk_kernel(
    const float* __restrict__ p1,
    const float* __restrict__ p2,
    float* __restrict__ out)
{
    extern __shared__ char dsm[];
    float4* sm   = (float4*)dsm;
    char*   mybuf = dsm + TILE * 16 + threadIdx.x * (SLOTS * 8);

    const int n  = blockIdx.x / BPB;
    const int q  = (blockIdx.x % BPB) * BLOCK + threadIdx.x;
    const bool active = (q < P1N);
    const int qc = active ? q : 0;  // clamped: inactive threads shadow query 0

    const float* p1r = p1 + ((size_t)n * P1N + qc) * 3;
    const float x1 = p1r[0], y1 = p1r[1], z1 = p1r[2];
    const float sq1 = sumsq3(x1, y1, z1);

    float dq[KK];
    int   iq[KK];
    const float INF = __int_as_float(0x7f800000);
#pragma unroll
    for (int i = 0; i < KK; i++) { dq[i] = INF; iq[i] = 0; }

    const float* p2b = p2 + (size_t)n * P2N * 3;

    float    worst = INF;
    unsigned cnt8  = 0;   // buffered items * 8 (byte offset)

    for (int t = 0; t < P2N; t += TILE) {
        __syncthreads();
        for (int i = threadIdx.x; i < TILE; i += BLOCK) {
            const float* pr = p2b + (size_t)(t + i) * 3;
            float x = pr[0], y = pr[1], z = pr[2];
            sm[i] = make_float4(x, y, z, sumsq3(x, y, z));
        }
        __syncthreads();

        for (int cb = 0; cb < TILE; cb += CHUNK) {
            bool direct = (t == 0) && (cb < 2 * CHUNK);
            if (direct) {
                // first 256 candidates: nearly always warp-hot; run the
                // identity-capable ladder unconditionally (no branches).
#pragma unroll 2
                for (int c = 0; c < CHUNK; c++) {
                    int jj = cb + c;
                    float4 s = sm[jj];
                    float inr = __fmaf_rn(z1, s.z, __fmaf_rn(y1, s.y,
                                 __fmul_rn(x1, s.x)));
                    float S = __fadd_rn(sq1, s.w);
                    float d = __fmaf_rn(-2.0f, inr, S);
                    float de = (d < worst) ? d : INF;
                    ladder(de, t + jj, dq, iq);
                    worst = dq[0];
                }
            } else {
                // buffered phase: branchless predicated push per candidate
#pragma unroll 4
                for (int c = 0; c < CHUNK; c++) {
                    int jj = cb + c;
                    float4 s = sm[jj];
                    float inr = __fmaf_rn(z1, s.z, __fmaf_rn(y1, s.y,
                                 __fmul_rn(x1, s.x)));
                    float S = __fadd_rn(sq1, s.w);
                    float d = __fmaf_rn(-2.0f, inr, S);
                    bool mine = d < worst;
                    if (mine && cnt8 == CAP * 8u) {
                        // rare (~3 events globally): in-order per-lane drain
#pragma unroll 1
                        for (unsigned k8 = 0; k8 < CAP * 8u; k8 += 8) {
                            float2 it = *(float2*)(mybuf + k8);
                            ladder(it.x, __float_as_int(it.y), dq, iq);
                        }
                        cnt8 = 0;
                        worst = dq[0];
                        mine = d < worst;
                    }
                    unsigned slot8 = mine ? cnt8 : CAP * 8u;  // dummy slot
                    *(float2*)(mybuf + slot8) =
                        make_float2(d, __int_as_float(t + jj));
                    cnt8 += mine ? 8u : 0u;
                }
                // uniform batched drain: lanes ladder together
                unsigned mx = __reduce_max_sync(0xffffffffu, cnt8);
#pragma unroll 1
                for (unsigned k8 = 0; k8 < mx; k8 += 8) {
                    float2 it = *(float2*)(mybuf + k8);
                    bool en = (k8 < cnt8);
                    float dd = en ? it.x : INF;   // INF -> identity ladder
                    ladder(dd, __float_as_int(it.y), dq, iq);
                }
                cnt8 = 0;
                worst = dq[0];
            }
        }
    }

    if (active) {
        const size_t base = ((size_t)n * P1N + q) * KK;
        const size_t NPK  = (size_t)NB * P1N * KK;
#pragma unroll
        for (int k = 0; k < KK; k++) {
            out[base + k]       = (float)iq[KK - 1 - k];
            out[NPK + base + k] = dq[KK - 1 - k];
        }
    }
}

extern "C" void kernel_launch(void* const* d_in, const int* in_sizes, int n_in,
                              void* d_out, int out_size)
{
    const float* p1 = (const float*)d_in[0];
    const float* p2 = (const float*)d_in[1];
    float* out = (float*)d_out;

    static bool attr_set = false;
    if (!attr_set) {
        cudaFuncSetAttribute(knn_topk_kernel,
                             cudaFuncAttributeMaxDynamicSharedMemorySize,
                             SMEM_BYTES);
        attr_set = true;
    }

    dim3 grid(NB * BPB);   // 148 blocks: one per SM, all SMs busy
    dim3 block(BLOCK);
    knn_topk_kernel<<<grid, block, SMEM_BYTES>>>(p1, p2, out);
}

// round 11
// speedup vs baseline: 2.4819x; 1.4918x over previous
#include <cuda_runtime.h>

#define NB     4
#define P1N    8192
#define P2N    8192
#define KK     16
#define TILE   1024          // candidates staged per tile
#define HALF   (TILE / 2)    // per-lane candidates per tile
#define CHUNKL 64            // per-lane chunk length between drains
#define BLOCK  128
#define BPB    128           // blocks per batch (128 * 64 queries = 8192)
#define CAP    32            // per-thread buffer capacity (items)
#define SLOTS  33            // CAP + dummy slot
#define SMEM_BYTES (TILE * 16 + BLOCK * SLOTS * 8)

// BIT-EXACT (proven R8): XLA small-row shuffle reduce (x^2+z^2)+y^2
__device__ __forceinline__ float sumsq3(float x, float y, float z) {
    return __fadd_rn(__fadd_rn(__fmul_rn(x, x), __fmul_rn(z, z)),
                     __fmul_rn(y, y));
}

// Exact insert into descending top-K. d==INF or d>=dq[0] -> identity.
// Strict '<' + ascending-j insertion order => lowest index wins ties.
__device__ __forceinline__ void ladder(float d, int j,
                                       float (&dq)[KK], int (&iq)[KK]) {
    bool pprev = d < dq[0];
#pragma unroll
    for (int i = 0; i < KK - 1; i++) {
        bool pi = d < dq[i + 1];
        float nd = pi ? dq[i + 1] : fminf(d, dq[i]);
        int   ni = pi ? iq[i + 1] : (pprev ? j : iq[i]);
        dq[i] = nd;
        iq[i] = ni;
        pprev = pi;
    }
    dq[KK - 1] = fminf(d, dq[KK - 1]);
    iq[KK - 1] = pprev ? j : iq[KK - 1];
}

// Tie-aware (lexicographic (d, j)) insert for the cross-slice merge.
__device__ __forceinline__ void ladder_tie(float d, int j,
                                           float (&dq)[KK], int (&iq)[KK]) {
    bool pprev = (d < dq[0]) || (d == dq[0] && j < iq[0]);
#pragma unroll
    for (int i = 0; i < KK - 1; i++) {
        bool pi = (d < dq[i + 1]) || (d == dq[i + 1] && j < iq[i + 1]);
        float nd = pi ? dq[i + 1] : (pprev ? d : dq[i]);
        int   ni = pi ? iq[i + 1] : (pprev ? j : iq[i]);
        dq[i] = nd;
        iq[i] = ni;
        pprev = pi;
    }
    dq[KK - 1] = pprev ? d : dq[KK - 1];
    iq[KK - 1] = pprev ? j : iq[KK - 1];
}

__global__ __launch_bounds__(BLOCK) void knn_topk_kernel(
    const float* __restrict__ p1,
    const float* __restrict__ p2,
    float* __restrict__ out)
{
    extern __shared__ char dsm[];
    float4* sm    = (float4*)dsm;
    char*   mybuf = dsm + TILE * 16 + threadIdx.x * (SLOTS * 8);

    const int par = threadIdx.x & 1;                    // slice parity
    const int n   = blockIdx.x >> 7;                    // batch
    const int qi  = (blockIdx.x & (BPB - 1)) * (BLOCK / 2) + (threadIdx.x >> 1);

    const float* p1r = p1 + ((size_t)n * P1N + qi) * 3;
    const float x1 = p1r[0], y1 = p1r[1], z1 = p1r[2];
    const float sq1 = sumsq3(x1, y1, z1);

    float dq[KK];
    int   iq[KK];
    const float INF = __int_as_float(0x7f800000);
#pragma unroll
    for (int i = 0; i < KK; i++) { dq[i] = INF; iq[i] = 0; }

    const float* p2b = p2 + (size_t)n * P2N * 3;

    float    worst = INF;
    unsigned cnt8  = 0;

    for (int t0 = 0; t0 < P2N; t0 += TILE) {
        __syncthreads();
        for (int i = threadIdx.x; i < TILE; i += BLOCK) {
            const float* pr = p2b + (size_t)(t0 + i) * 3;
            float x = pr[0], y = pr[1], z = pr[2];
            sm[i] = make_float4(x, y, z, sumsq3(x, y, z));
        }
        __syncthreads();

        for (int cb = 0; cb < HALF; cb += CHUNKL) {
            if (t0 == 0 && cb == 0) {
                // first 64 per-lane candidates: essentially always warp-hot,
                // run identity-capable ladder unconditionally (branch-free).
#pragma unroll 1
                for (int c = 0; c < CHUNKL; c++) {
                    float4 s = sm[2 * c + par];
                    float inr = __fmaf_rn(z1, s.z, __fmaf_rn(y1, s.y,
                                 __fmul_rn(x1, s.x)));
                    float d = __fmaf_rn(-2.0f, inr, __fadd_rn(sq1, s.w));
                    ladder((d < worst) ? d : INF, t0 + 2 * c + par, dq, iq);
                    worst = dq[0];
                }
            } else {
                for (int g = 0; g < CHUNKL; g += 4) {
                    // headroom check once per 4: rare per-lane full drain
                    if (cnt8 >= (CAP - 4) * 8u) {
#pragma unroll 1
                        for (unsigned k8 = 0; k8 < cnt8; k8 += 8) {
                            float2 it = *(float2*)(mybuf + k8);
                            ladder(it.x, __float_as_int(it.y), dq, iq);
                        }
                        cnt8 = 0;
                        worst = dq[0];
                    }
#pragma unroll
                    for (int u = 0; u < 4; u++) {
                        int c = cb + g + u;
                        float4 s = sm[2 * c + par];
                        float inr = __fmaf_rn(z1, s.z, __fmaf_rn(y1, s.y,
                                     __fmul_rn(x1, s.x)));
                        float d = __fmaf_rn(-2.0f, inr, __fadd_rn(sq1, s.w));
                        bool mine = d < worst;
                        unsigned slot8 = mine ? cnt8 : CAP * 8u;  // dummy
                        *(float2*)(mybuf + slot8) =
                            make_float2(d, __int_as_float(t0 + 2 * c + par));
                        cnt8 += mine ? 8u : 0u;
                    }
                }
                // uniform batched drain: lanes ladder together
                unsigned mx = __reduce_max_sync(0xffffffffu, cnt8);
#pragma unroll 1
                for (unsigned k8 = 0; k8 < mx; k8 += 8) {
                    float2 it = *(float2*)(mybuf + k8);
                    float dd = (k8 < cnt8) ? it.x : INF;
                    ladder(dd, __float_as_int(it.y), dq, iq);
                }
                cnt8 = 0;
                worst = dq[0];
            }
        }
    }

    // merge odd-lane (odd-j slice) results into even lane; tie-aware
    // lexicographic insert keeps global lowest-index-wins semantics.
    bool recv = (par == 0);
#pragma unroll 1
    for (int k = 0; k < KK; k++) {
        float md = __shfl_down_sync(0xffffffffu, dq[k], 1);
        int   mj = __shfl_down_sync(0xffffffffu, iq[k], 1);
        ladder_tie(recv ? md : INF, mj, dq, iq);
    }

    if (recv) {
        const size_t base = ((size_t)n * P1N + qi) * KK;
        const size_t NPK  = (size_t)NB * P1N * KK;
#pragma unroll
        for (int k = 0; k < KK; k++) {
            out[base + k]       = (float)iq[KK - 1 - k];
            out[NPK + base + k] = dq[KK - 1 - k];
        }
    }
}

extern "C" void kernel_launch(void* const* d_in, const int* in_sizes, int n_in,
                              void* d_out, int out_size)
{
    const float* p1 = (const float*)d_in[0];
    const float* p2 = (const float*)d_in[1];
    float* out = (float*)d_out;

    static bool attr_set = false;
    if (!attr_set) {
        cudaFuncSetAttribute(knn_topk_kernel,
                             cudaFuncAttributeMaxDynamicSharedMemorySize,
                             SMEM_BYTES);
        attr_set = true;
    }

    dim3 grid(NB * BPB);    // 512 blocks -> ~3.5 blocks/SM, 2048 warps
    dim3 block(BLOCK);
    knn_topk_kernel<<<grid, block, SMEM_BYTES>>>(p1, p2, out);
}

// round 13
// speedup vs baseline: 2.5023x; 1.0082x over previous
#include <cuda_runtime.h>

#define NB     4
#define P1N    8192
#define P2N    8192
#define KK     16
#define TILE   1024          // candidates staged per tile
#define QPB    64            // queries per block
#define BLOCK  256           // 4 threads (slices) per query
#define BPB    (P1N / QPB)   // 128 blocks per batch
#define PERL   (TILE / 4)    // per-lane candidates per tile = 256
#define CHUNKL 64            // per-lane chunk between batched drains
#define CAP    28            // per-thread index-buffer capacity
#define SLOTS  29            // CAP + dummy slot
#define SMEM_BYTES (TILE * 16 + BLOCK * SLOTS * 4)

// BIT-EXACT (proven R8): XLA small-row shuffle reduce (x^2+z^2)+y^2
__device__ __forceinline__ float sumsq3(float x, float y, float z) {
    return __fadd_rn(__fadd_rn(__fmul_rn(x, x), __fmul_rn(z, z)),
                     __fmul_rn(y, y));
}

// Exact insert into descending top-K. d==INF or d>=dq[0] -> identity.
// Strict '<' + ascending-j order => lowest index wins ties (== lex (d,j)).
__device__ __forceinline__ void ladder(float d, int j,
                                       float (&dq)[KK], int (&iq)[KK]) {
    bool pprev = d < dq[0];
#pragma unroll
    for (int i = 0; i < KK - 1; i++) {
        bool pi = d < dq[i + 1];
        float nd = pi ? dq[i + 1] : fminf(d, dq[i]);
        int   ni = pi ? iq[i + 1] : (pprev ? j : iq[i]);
        dq[i] = nd;
        iq[i] = ni;
        pprev = pi;
    }
    dq[KK - 1] = fminf(d, dq[KK - 1]);
    iq[KK - 1] = pprev ? j : iq[KK - 1];
}

// Lexicographic-(d,j) insert for cross-slice merge. d==INF -> identity.
__device__ __forceinline__ void ladder_tie(float d, int j,
                                           float (&dq)[KK], int (&iq)[KK]) {
    bool pprev = (d < dq[0]) || (d == dq[0] && j < iq[0]);
#pragma unroll
    for (int i = 0; i < KK - 1; i++) {
        bool pi = (d < dq[i + 1]) || (d == dq[i + 1] && j < iq[i + 1]);
        float nd = pi ? dq[i + 1] : (pprev ? d : dq[i]);
        int   ni = pi ? iq[i + 1] : (pprev ? j : iq[i]);
        dq[i] = nd;
        iq[i] = ni;
        pprev = pi;
    }
    dq[KK - 1] = pprev ? d : dq[KK - 1];
    iq[KK - 1] = pprev ? j : iq[KK - 1];
}

__global__ __launch_bounds__(BLOCK, 4) void knn_topk_kernel(
    const float* __restrict__ p1,
    const float* __restrict__ p2,
    float* __restrict__ out)
{
    extern __shared__ char dsm[];
    float4*   sm    = (float4*)dsm;
    unsigned* mybuf = (unsigned*)(dsm + TILE * 16) + threadIdx.x * SLOTS;

    const int slice = threadIdx.x & 3;                 // j mod 4 slice
    const int n     = blockIdx.x / BPB;                // batch
    const int qi    = (blockIdx.x % BPB) * QPB + (threadIdx.x >> 2);

    const float* p1r = p1 + ((size_t)n * P1N + qi) * 3;
    const float x1 = p1r[0], y1 = p1r[1], z1 = p1r[2];
    const float sq1 = sumsq3(x1, y1, z1);

    float dq[KK];
    int   iq[KK];
    const float INF = __int_as_float(0x7f800000);
#pragma unroll
    for (int i = 0; i < KK; i++) { dq[i] = INF; iq[i] = 0; }

    const float* p2b = p2 + (size_t)n * P2N * 3;

    float    worst = INF;
    unsigned cnt   = 0;

    for (int t0 = 0; t0 < P2N; t0 += TILE) {
        __syncthreads();
        for (int i = threadIdx.x; i < TILE; i += BLOCK) {
            const float* pr = p2b + (size_t)(t0 + i) * 3;
            float x = pr[0], y = pr[1], z = pr[2];
            sm[i] = make_float4(x, y, z, sumsq3(x, y, z));
        }
        __syncthreads();

        for (int cb = 0; cb < PERL; cb += CHUNKL) {
            if (t0 == 0 && cb == 0) {
                // first 64 per-lane candidates: nearly always hot; run the
                // identity-capable ladder unconditionally (branch-free).
#pragma unroll 1
                for (int c = 0; c < CHUNKL; c++) {
                    int li = 4 * c + slice;
                    float4 s = sm[li];
                    float inr = __fmaf_rn(z1, s.z, __fmaf_rn(y1, s.y,
                                 __fmul_rn(x1, s.x)));
                    float d = __fmaf_rn(-2.0f, inr, __fadd_rn(sq1, s.w));
                    ladder((d < worst) ? d : INF, t0 + li, dq, iq);
                    worst = dq[0];
                }
            } else {
                for (int g = 0; g < CHUNKL; g += 8) {
                    // headroom check per 8: very rare per-lane full drain
                    if (cnt >= CAP - 8) {
#pragma unroll 1
                        for (unsigned k = 0; k < cnt; k++) {
                            unsigned li = mybuf[k] & (TILE - 1);
                            float4 s = sm[li];
                            float inr = __fmaf_rn(z1, s.z, __fmaf_rn(y1, s.y,
                                         __fmul_rn(x1, s.x)));
                            float d = __fmaf_rn(-2.0f, inr,
                                                __fadd_rn(sq1, s.w));
                            ladder(d, t0 + (int)li, dq, iq);
                        }
                        cnt = 0;
                        worst = dq[0];
                    }
#pragma unroll
                    for (int u = 0; u < 8; u++) {
                        int li = 4 * (cb + g + u) + slice;
                        float4 s = sm[li];
                        float inr = __fmaf_rn(z1, s.z, __fmaf_rn(y1, s.y,
                                     __fmul_rn(x1, s.x)));
                        float d = __fmaf_rn(-2.0f, inr, __fadd_rn(sq1, s.w));
                        bool mine = d < worst;
                        mybuf[mine ? cnt : CAP] = (unsigned)li;  // dummy slot
                        cnt += mine ? 1u : 0u;
                    }
                }
                // uniform batched drain: lanes ladder together, d recomputed
                // from the resident tile (bit-identical ops).
                unsigned mx = __reduce_max_sync(0xffffffffu, cnt);
#pragma unroll 1
                for (unsigned k = 0; k < mx; k++) {
                    unsigned li = mybuf[k] & (TILE - 1);
                    float4 s = sm[li];
                    float inr = __fmaf_rn(z1, s.z, __fmaf_rn(y1, s.y,
                                 __fmul_rn(x1, s.x)));
                    float d = __fmaf_rn(-2.0f, inr, __fadd_rn(sq1, s.w));
                    ladder((k < cnt) ? d : INF, t0 + (int)li, dq, iq);
                }
                cnt = 0;
                worst = dq[0];
            }
        }
    }

    // ---- cross-slice merge: two ONE-DIRECTIONAL rounds (no butterfly).
    // Senders insert INF (identity) so their lists stay frozen while the
    // receiver shuffles their 16 entries over 16 iterations (R11-proven).
    // Round 1: slices {0,2} <- {1,3}
#pragma unroll
    for (int k = 0; k < KK; k++) {
        float md = __shfl_xor_sync(0xffffffffu, dq[k], 1);
        int   mj = __shfl_xor_sync(0xffffffffu, iq[k], 1);
        ladder_tie(((slice & 1) == 0) ? md : INF, mj, dq, iq);
    }
    // Round 2: slice 0 <- slice 2 (slice 2's merged list is frozen here)
#pragma unroll
    for (int k = 0; k < KK; k++) {
        float md = __shfl_xor_sync(0xffffffffu, dq[k], 2);
        int   mj = __shfl_xor_sync(0xffffffffu, iq[k], 2);
        ladder_tie((slice == 0) ? md : INF, mj, dq, iq);
    }

    if (slice == 0) {
        const size_t base = ((size_t)n * P1N + qi) * KK;
        const size_t NPK  = (size_t)NB * P1N * KK;
#pragma unroll
        for (int k = 0; k < KK; k++) {
            out[base + k]       = (float)iq[KK - 1 - k];
            out[NPK + base + k] = dq[KK - 1 - k];
        }
    }
}

extern "C" void kernel_launch(void* const* d_in, const int* in_sizes, int n_in,
                              void* d_out, int out_size)
{
    const float* p1 = (const float*)d_in[0];
    const float* p2 = (const float*)d_in[1];
    float* out = (float*)d_out;

    static bool attr_set = false;
    if (!attr_set) {
        cudaFuncSetAttribute(knn_topk_kernel,
                             cudaFuncAttributeMaxDynamicSharedMemorySize,
                             SMEM_BYTES);
        attr_set = true;
    }

    dim3 grid(NB * BPB);    // 512 blocks, 4/SM, single wave, 4096 warps
    dim3 block(BLOCK);
    knn_topk_kernel<<<grid, block, SMEM_BYTES>>>(p1, p2, out);
}

// round 14
// speedup vs baseline: 2.7667x; 1.1056x over previous
#include <cuda_runtime.h>

#define NB     4
#define P1N    8192
#define P2N    8192
#define KK     16
#define TILE   1024          // candidates staged per tile
#define QPB    64            // queries per block
#define BLOCK  256           // 4 threads (slices) per query
#define BPB    (P1N / QPB)   // 128 blocks per batch
#define PERL   (TILE / 4)    // per-lane candidates per tile = 256
#define CHUNKL 64            // per-lane chunk between batched drains
#define CAP    28            // per-thread index-buffer capacity
#define SLOTS  29            // CAP + dummy slot
#define SMEM_BYTES (TILE * 16 + BLOCK * SLOTS * 4)

// BIT-EXACT (proven R8): XLA small-row shuffle reduce (x^2+z^2)+y^2
__device__ __forceinline__ float sumsq3(float x, float y, float z) {
    return __fadd_rn(__fadd_rn(__fmul_rn(x, x), __fmul_rn(z, z)),
                     __fmul_rn(y, y));
}

// Exact insert into descending top-K. d==INF or d>=dq[0] -> identity.
// Strict '<' + ascending-j order => lowest index wins ties (== lex (d,j)).
__device__ __forceinline__ void ladder(float d, int j,
                                       float (&dq)[KK], int (&iq)[KK]) {
    bool pprev = d < dq[0];
#pragma unroll
    for (int i = 0; i < KK - 1; i++) {
        bool pi = d < dq[i + 1];
        float nd = pi ? dq[i + 1] : fminf(d, dq[i]);
        int   ni = pi ? iq[i + 1] : (pprev ? j : iq[i]);
        dq[i] = nd;
        iq[i] = ni;
        pprev = pi;
    }
    dq[KK - 1] = fminf(d, dq[KK - 1]);
    iq[KK - 1] = pprev ? j : iq[KK - 1];
}

// Lexicographic-(d,j) insert for cross-slice merge. d==INF -> identity.
__device__ __forceinline__ void ladder_tie(float d, int j,
                                           float (&dq)[KK], int (&iq)[KK]) {
    bool pprev = (d < dq[0]) || (d == dq[0] && j < iq[0]);
#pragma unroll
    for (int i = 0; i < KK - 1; i++) {
        bool pi = (d < dq[i + 1]) || (d == dq[i + 1] && j < iq[i + 1]);
        float nd = pi ? dq[i + 1] : (pprev ? d : dq[i]);
        int   ni = pi ? iq[i + 1] : (pprev ? j : iq[i]);
        dq[i] = nd;
        iq[i] = ni;
        pprev = pi;
    }
    dq[KK - 1] = pprev ? d : dq[KK - 1];
    iq[KK - 1] = pprev ? j : iq[KK - 1];
}

// W* = min of the 4 slice-worsts of this query (slices = adjacent lanes).
__device__ __forceinline__ float slice_min4(float w) {
    w = fminf(w, __shfl_xor_sync(0xffffffffu, w, 1));
    w = fminf(w, __shfl_xor_sync(0xffffffffu, w, 2));
    return w;
}

__global__ __launch_bounds__(BLOCK, 4) void knn_topk_kernel(
    const float* __restrict__ p1,
    const float* __restrict__ p2,
    float* __restrict__ out)
{
    extern __shared__ char dsm[];
    float4*   sm    = (float4*)dsm;
    unsigned* mybuf = (unsigned*)(dsm + TILE * 16) + threadIdx.x * SLOTS;

    const int slice = threadIdx.x & 3;                 // j mod 4 slice
    const int n     = blockIdx.x / BPB;                // batch
    const int qi    = (blockIdx.x % BPB) * QPB + (threadIdx.x >> 2);

    const float* p1r = p1 + ((size_t)n * P1N + qi) * 3;
    const float x1 = p1r[0], y1 = p1r[1], z1 = p1r[2];
    const float sq1 = sumsq3(x1, y1, z1);

    float dq[KK];
    int   iq[KK];
    const float INF = __int_as_float(0x7f800000);
#pragma unroll
    for (int i = 0; i < KK; i++) { dq[i] = INF; iq[i] = 0; }

    const float* p2b = p2 + (size_t)n * P2N * 3;

    float    wstar = INF;   // query-global prune bound (>= global 16th, always)
    unsigned cnt   = 0;

    for (int t0 = 0; t0 < P2N; t0 += TILE) {
        __syncthreads();
        for (int i = threadIdx.x; i < TILE; i += BLOCK) {
            const float* pr = p2b + (size_t)(t0 + i) * 3;
            float x = pr[0], y = pr[1], z = pr[2];
            sm[i] = make_float4(x, y, z, sumsq3(x, y, z));
        }
        __syncthreads();

        for (int cb = 0; cb < PERL; cb += CHUNKL) {
            if (t0 == 0 && cb == 0) {
                // first 64 per-lane candidates: nearly always hot; run the
                // identity-capable ladder unconditionally (branch-free).
                float worst = INF;
#pragma unroll 1
                for (int c = 0; c < CHUNKL; c++) {
                    int li = 4 * c + slice;
                    float4 s = sm[li];
                    float inr = __fmaf_rn(z1, s.z, __fmaf_rn(y1, s.y,
                                 __fmul_rn(x1, s.x)));
                    float d = __fmaf_rn(-2.0f, inr, __fadd_rn(sq1, s.w));
                    ladder((d < worst) ? d : INF, t0 + li, dq, iq);
                    worst = dq[0];
                }
                wstar = slice_min4(dq[0]);
            } else {
                for (int g = 0; g < CHUNKL; g += 8) {
                    // headroom check per 8: very rare per-lane full drain
                    if (cnt >= CAP - 8) {
#pragma unroll 1
                        for (unsigned k = 0; k < cnt; k++) {
                            unsigned li = mybuf[k] & (TILE - 1);
                            float4 s = sm[li];
                            float inr = __fmaf_rn(z1, s.z, __fmaf_rn(y1, s.y,
                                         __fmul_rn(x1, s.x)));
                            float d = __fmaf_rn(-2.0f, inr,
                                                __fadd_rn(sq1, s.w));
                            ladder(d, t0 + (int)li, dq, iq);
                        }
                        cnt = 0;
                        // divergent context: no shuffle here; wstar stays
                        // stale (still a valid upper bound -> safe gate).
                    }
#pragma unroll
                    for (int u = 0; u < 8; u++) {
                        int li = 4 * (cb + g + u) + slice;
                        float4 s = sm[li];
                        float inr = __fmaf_rn(z1, s.z, __fmaf_rn(y1, s.y,
                                     __fmul_rn(x1, s.x)));
                        float d = __fmaf_rn(-2.0f, inr, __fadd_rn(sq1, s.w));
                        // gate vs query-global bound; '<=' keeps boundary
                        // ties so index resolution stays exact.
                        bool mine = d <= wstar;
                        mybuf[mine ? cnt : CAP] = (unsigned)li;  // dummy slot
                        cnt += mine ? 1u : 0u;
                    }
                }
                // uniform batched drain: lanes ladder together, d recomputed
                // from the resident tile (bit-identical ops).
                unsigned mx = __reduce_max_sync(0xffffffffu, cnt);
#pragma unroll 1
                for (unsigned k = 0; k < mx; k++) {
                    unsigned li = mybuf[k] & (TILE - 1);
                    float4 s = sm[li];
                    float inr = __fmaf_rn(z1, s.z, __fmaf_rn(y1, s.y,
                                 __fmul_rn(x1, s.x)));
                    float d = __fmaf_rn(-2.0f, inr, __fadd_rn(sq1, s.w));
                    ladder((k < cnt) ? d : INF, t0 + (int)li, dq, iq);
                }
                cnt = 0;
                wstar = slice_min4(dq[0]);   // uniform: tighten shared bound
            }
        }
    }

    // ---- cross-slice merge: two ONE-DIRECTIONAL rounds (R13-proven).
    // Round 1: slices {0,2} <- {1,3}
#pragma unroll
    for (int k = 0; k < KK; k++) {
        float md = __shfl_xor_sync(0xffffffffu, dq[k], 1);
        int   mj = __shfl_xor_sync(0xffffffffu, iq[k], 1);
        ladder_tie(((slice & 1) == 0) ? md : INF, mj, dq, iq);
    }
    // Round 2: slice 0 <- slice 2 (slice 2's merged list frozen here)
#pragma unroll
    for (int k = 0; k < KK; k++) {
        float md = __shfl_xor_sync(0xffffffffu, dq[k], 2);
        int   mj = __shfl_xor_sync(0xffffffffu, iq[k], 2);
        ladder_tie((slice == 0) ? md : INF, mj, dq, iq);
    }

    if (slice == 0) {
        const size_t base = ((size_t)n * P1N + qi) * KK;
        const size_t NPK  = (size_t)NB * P1N * KK;
#pragma unroll
        for (int k = 0; k < KK; k++) {
            out[base + k]       = (float)iq[KK - 1 - k];
            out[NPK + base + k] = dq[KK - 1 - k];
        }
    }
}

extern "C" void kernel_launch(void* const* d_in, const int* in_sizes, int n_in,
                              void* d_out, int out_size)
{
    const float* p1 = (const float*)d_in[0];
    const float* p2 = (const float*)d_in[1];
    float* out = (float*)d_out;

    static bool attr_set = false;
    if (!attr_set) {
        cudaFuncSetAttribute(knn_topk_kernel,
                             cudaFuncAttributeMaxDynamicSharedMemorySize,
                             SMEM_BYTES);
        attr_set = true;
    }

    dim3 grid(NB * BPB);    // 512 blocks, single wave, 4096 warps
    dim3 block(BLOCK);
    knn_topk_kernel<<<grid, block, SMEM_BYTES>>>(p1, p2, out);
}

// round 15
// speedup vs baseline: 2.8899x; 1.0445x over previous
#include <cuda_runtime.h>

#define NB      4
#define P1N     8192
#define P2N     8192
#define KK      16
#define TILE    1024
#define QPB     64
#define BLOCK   256            // 4 slices per query
#define BPB     (P1N / QPB)    // 128 blocks per batch
#define PAIRS   (TILE / 2)     // 512 pairs per tile
#define CHUNKP  32             // pairs per chunk per lane (= 64 candidates)
#define NCHUNK  4              // chunks per tile per lane (128 pairs/lane)
#define SMEM_BYTES (PAIRS * 32)

// BIT-EXACT (proven R8): XLA small-row shuffle reduce (x^2+z^2)+y^2
__device__ __forceinline__ float sumsq3(float x, float y, float z) {
    return __fadd_rn(__fadd_rn(__fmul_rn(x, x), __fmul_rn(z, z)),
                     __fmul_rn(y, y));
}

__device__ __forceinline__ unsigned long long pack2(float a, float b) {
    unsigned long long r;
    asm("mov.b64 %0, {%1, %2};" : "=l"(r) : "f"(a), "f"(b));
    return r;
}

// packed distance for a candidate pair; per-element bit-identical to the
// scalar chain: d = fma(-2, fma(z1,z, fma(y1,y, mul(x1,x))), add(sq1,q))
__device__ __forceinline__ void dist2(
    unsigned long long xp, unsigned long long yp, unsigned long long zp,
    unsigned long long qp, unsigned long long X1, unsigned long long Y1,
    unsigned long long Z1, unsigned long long SQ1, unsigned long long N2,
    float& d0, float& d1)
{
    asm("{\n\t"
        ".reg .b64 t, s;\n\t"
        "mul.rn.f32x2 t, %2, %3;\n\t"
        "fma.rn.f32x2 t, %4, %5, t;\n\t"
        "fma.rn.f32x2 t, %6, %7, t;\n\t"
        "add.rn.f32x2 s, %8, %9;\n\t"
        "fma.rn.f32x2 t, %10, t, s;\n\t"
        "mov.b64 {%0, %1}, t;\n\t"
        "}"
        : "=f"(d0), "=f"(d1)
        : "l"(X1), "l"(xp), "l"(Y1), "l"(yp), "l"(Z1), "l"(zp),
          "l"(SQ1), "l"(qp), "l"(N2));
}

__device__ __forceinline__ float uhalf(unsigned long long u, int h) {
    return __int_as_float((int)(h ? (u >> 32) : (u & 0xffffffffu)));
}

// Exact insert into descending top-K. d==INF or d>=dq[0] -> identity.
// Strict '<' + ascending-j order => lowest index wins ties (== lex (d,j)).
__device__ __forceinline__ void ladder(float d, int j,
                                       float (&dq)[KK], int (&iq)[KK]) {
    bool pprev = d < dq[0];
#pragma unroll
    for (int i = 0; i < KK - 1; i++) {
        bool pi = d < dq[i + 1];
        float nd = pi ? dq[i + 1] : fminf(d, dq[i]);
        int   ni = pi ? iq[i + 1] : (pprev ? j : iq[i]);
        dq[i] = nd;
        iq[i] = ni;
        pprev = pi;
    }
    dq[KK - 1] = fminf(d, dq[KK - 1]);
    iq[KK - 1] = pprev ? j : iq[KK - 1];
}

// Lexicographic-(d,j) insert for cross-slice merge. d==INF -> identity.
__device__ __forceinline__ void ladder_tie(float d, int j,
                                           float (&dq)[KK], int (&iq)[KK]) {
    bool pprev = (d < dq[0]) || (d == dq[0] && j < iq[0]);
#pragma unroll
    for (int i = 0; i < KK - 1; i++) {
        bool pi = (d < dq[i + 1]) || (d == dq[i + 1] && j < iq[i + 1]);
        float nd = pi ? dq[i + 1] : (pprev ? d : dq[i]);
        int   ni = pi ? iq[i + 1] : (pprev ? j : iq[i]);
        dq[i] = nd;
        iq[i] = ni;
        pprev = pi;
    }
    dq[KK - 1] = pprev ? d : dq[KK - 1];
    iq[KK - 1] = pprev ? j : iq[KK - 1];
}

// W* = min of the 4 slice-worsts of this query (slices = adjacent lanes).
__device__ __forceinline__ float slice_min4(float w) {
    w = fminf(w, __shfl_xor_sync(0xffffffffu, w, 1));
    w = fminf(w, __shfl_xor_sync(0xffffffffu, w, 2));
    return w;
}

__global__ __launch_bounds__(BLOCK, 4) void knn_topk_kernel(
    const float* __restrict__ p1,
    const float* __restrict__ p2,
    float* __restrict__ out)
{
    extern __shared__ char dsm[];

    const int slice = threadIdx.x & 3;
    const int n     = blockIdx.x / BPB;
    const int qi    = (blockIdx.x % BPB) * QPB + (threadIdx.x >> 2);

    const float* p1r = p1 + ((size_t)n * P1N + qi) * 3;
    const float x1 = p1r[0], y1 = p1r[1], z1 = p1r[2];
    const float sq1 = sumsq3(x1, y1, z1);

    const unsigned long long X1p  = pack2(x1, x1);
    const unsigned long long Y1p  = pack2(y1, y1);
    const unsigned long long Z1p  = pack2(z1, z1);
    const unsigned long long SQ1p = pack2(sq1, sq1);
    const unsigned long long N2p  = pack2(-2.0f, -2.0f);

    float dq[KK];
    int   iq[KK];
    const float INF = __int_as_float(0x7f800000);
#pragma unroll
    for (int i = 0; i < KK; i++) { dq[i] = INF; iq[i] = 0; }

    const float* p2b = p2 + (size_t)n * P2N * 3;
    float wstar = INF;

    for (int t0 = 0; t0 < P2N; t0 += TILE) {
        __syncthreads();
        // stage pairs: [x0,x1,y0,y1 | z0,z1,q0,q1], 32B per pair
        for (int k = threadIdx.x; k < PAIRS; k += BLOCK) {
            const float2* pr2 = (const float2*)(p2b + (size_t)(t0 + 2 * k) * 3);
            float2 a = pr2[0], b = pr2[1], c = pr2[2];
            // a=(x0,y0) b=(z0,x1) c=(y1,z1)
            float q0 = sumsq3(a.x, a.y, b.x);
            float q1 = sumsq3(b.y, c.x, c.y);
            float4* dst = (float4*)dsm + 2 * k;
            dst[0] = make_float4(a.x, b.y, a.y, c.x);   // x0,x1,y0,y1
            dst[1] = make_float4(b.x, c.y, q0, q1);     // z0,z1,q0,q1
        }
        __syncthreads();

        for (int cc = 0; cc < NCHUNK; cc++) {
            // lane's pairs: tile pair index pi = 4*p + slice, p = cc*32+u
            const char* base = dsm + ((4 * (cc * CHUNKP) + slice) * 32);
            unsigned m0 = 0, m1 = 0;
#pragma unroll 8
            for (int u = 0; u < CHUNKP; u++) {
                const ulonglong2* pp =
                    (const ulonglong2*)(base + (size_t)u * 128);
                ulonglong2 A = pp[0];   // (x0,x1),(y0,y1)
                ulonglong2 B = pp[1];   // (z0,z1),(q0,q1)
                float d0, d1;
                dist2(A.x, A.y, B.x, B.y, X1p, Y1p, Z1p, SQ1p, N2p, d0, d1);
                // '<=' keeps boundary ties so index resolution stays exact
                if (u < 16) {
                    if (d0 <= wstar) m0 |= (1u << (2 * u));
                    if (d1 <= wstar) m0 |= (1u << (2 * u + 1));
                } else {
                    if (d0 <= wstar) m1 |= (1u << (2 * u - 32));
                    if (d1 <= wstar) m1 |= (1u << (2 * u - 31));
                }
            }

            // uniform drain: ascending bit order == ascending j per lane
            int cnt = __popc(m0) + __popc(m1);
            int mx  = (int)__reduce_max_sync(0xffffffffu, (unsigned)cnt);
            unsigned long long m =
                ((unsigned long long)m1 << 32) | (unsigned long long)m0;
#pragma unroll 1
            for (int k = 0; k < mx; k++) {
                bool en = (k < cnt);
                int  b  = en ? (__ffsll((long long)m) - 1) : 0;
                m &= m - 1;
                const ulonglong2* pp =
                    (const ulonglong2*)(base + (size_t)(b >> 1) * 128);
                ulonglong2 A = pp[0];
                ulonglong2 B = pp[1];
                int h = b & 1;
                float x = uhalf(A.x, h), y = uhalf(A.y, h);
                float z = uhalf(B.x, h), q = uhalf(B.y, h);
                float inr = __fmaf_rn(z1, z, __fmaf_rn(y1, y,
                             __fmul_rn(x1, x)));
                float d = __fmaf_rn(-2.0f, inr, __fadd_rn(sq1, q));
                int li = 8 * (cc * CHUNKP + (b >> 1)) + 2 * slice + h;
                ladder(en ? d : INF, t0 + li, dq, iq);
            }
            wstar = slice_min4(dq[0]);
        }
    }

    // cross-slice merge: two ONE-DIRECTIONAL rounds (R13-proven exact).
#pragma unroll
    for (int k = 0; k < KK; k++) {
        float md = __shfl_xor_sync(0xffffffffu, dq[k], 1);
        int   mj = __shfl_xor_sync(0xffffffffu, iq[k], 1);
        ladder_tie(((slice & 1) == 0) ? md : INF, mj, dq, iq);
    }
#pragma unroll
    for (int k = 0; k < KK; k++) {
        float md = __shfl_xor_sync(0xffffffffu, dq[k], 2);
        int   mj = __shfl_xor_sync(0xffffffffu, iq[k], 2);
        ladder_tie((slice == 0) ? md : INF, mj, dq, iq);
    }

    if (slice == 0) {
        const size_t base = ((size_t)n * P1N + qi) * KK;
        const size_t NPK  = (size_t)NB * P1N * KK;
#pragma unroll
        for (int k = 0; k < KK; k++) {
            out[base + k]       = (float)iq[KK - 1 - k];
            out[NPK + base + k] = dq[KK - 1 - k];
        }
    }
}

extern "C" void kernel_launch(void* const* d_in, const int* in_sizes, int n_in,
                              void* d_out, int out_size)
{
    const float* p1 = (const float*)d_in[0];
    const float* p2 = (const float*)d_in[1];
    float* out = (float*)d_out;

    static bool attr_set = false;
    if (!attr_set) {
        cudaFuncSetAttribute(knn_topk_kernel,
                             cudaFuncAttributeMaxDynamicSharedMemorySize,
                             SMEM_BYTES);
        attr_set = true;
    }

    dim3 grid(NB * BPB);
    dim3 block(BLOCK);
    knn_topk_kernel<<<grid, block, SMEM_BYTES>>>(p1, p2, out);
}

// round 16
// speedup vs baseline: 3.1460x; 1.0886x over previous
#include <cuda_runtime.h>

#define NB      4
#define P1N     8192
#define P2N     8192
#define KK      16
#define TILE    1024
#define QPB     64
#define BLOCK   256            // 4 slices per query
#define BPB     (P1N / QPB)    // 128 blocks per batch
#define PAIRS   (TILE / 2)     // 512 pairs per tile
#define CHUNKP  32             // pairs per chunk per lane (= 64 candidates)
#define NCHUNK  4              // chunks per tile per lane
#define SMEM_BYTES (PAIRS * 32)

// BIT-EXACT (proven R8): XLA small-row shuffle reduce (x^2+z^2)+y^2
__device__ __forceinline__ float sumsq3(float x, float y, float z) {
    return __fadd_rn(__fadd_rn(__fmul_rn(x, x), __fmul_rn(z, z)),
                     __fmul_rn(y, y));
}

__device__ __forceinline__ unsigned long long pack2(float a, float b) {
    unsigned long long r;
    asm("mov.b64 %0, {%1, %2};" : "=l"(r) : "f"(a), "f"(b));
    return r;
}

// packed distance for a candidate pair; per-element bit-identical to the
// scalar chain: d = fma(-2, fma(z1,z, fma(y1,y, mul(x1,x))), add(sq1,q))
__device__ __forceinline__ void dist2(
    unsigned long long xp, unsigned long long yp, unsigned long long zp,
    unsigned long long qp, unsigned long long X1, unsigned long long Y1,
    unsigned long long Z1, unsigned long long SQ1, unsigned long long N2,
    float& d0, float& d1)
{
    asm("{\n\t"
        ".reg .b64 t, s;\n\t"
        "mul.rn.f32x2 t, %2, %3;\n\t"
        "fma.rn.f32x2 t, %4, %5, t;\n\t"
        "fma.rn.f32x2 t, %6, %7, t;\n\t"
        "add.rn.f32x2 s, %8, %9;\n\t"
        "fma.rn.f32x2 t, %10, t, s;\n\t"
        "mov.b64 {%0, %1}, t;\n\t"
        "}"
        : "=f"(d0), "=f"(d1)
        : "l"(X1), "l"(xp), "l"(Y1), "l"(yp), "l"(Z1), "l"(zp),
          "l"(SQ1), "l"(qp), "l"(N2));
}

__device__ __forceinline__ float uhalf(unsigned long long u, int h) {
    return __int_as_float((int)(h ? (u >> 32) : (u & 0xffffffffu)));
}

// Exact insert into descending top-K. d==INF or d>=dq[0] -> identity.
// Strict '<' + ascending-j order => lowest index wins ties (== lex (d,j)).
__device__ __forceinline__ void ladder(float d, int j,
                                       float (&dq)[KK], int (&iq)[KK]) {
    bool pprev = d < dq[0];
#pragma unroll
    for (int i = 0; i < KK - 1; i++) {
        bool pi = d < dq[i + 1];
        float nd = pi ? dq[i + 1] : fminf(d, dq[i]);
        int   ni = pi ? iq[i + 1] : (pprev ? j : iq[i]);
        dq[i] = nd;
        iq[i] = ni;
        pprev = pi;
    }
    dq[KK - 1] = fminf(d, dq[KK - 1]);
    iq[KK - 1] = pprev ? j : iq[KK - 1];
}

// Lexicographic-(d,j) insert for cross-slice merge. d==INF -> identity.
__device__ __forceinline__ void ladder_tie(float d, int j,
                                           float (&dq)[KK], int (&iq)[KK]) {
    bool pprev = (d < dq[0]) || (d == dq[0] && j < iq[0]);
#pragma unroll
    for (int i = 0; i < KK - 1; i++) {
        bool pi = (d < dq[i + 1]) || (d == dq[i + 1] && j < iq[i + 1]);
        float nd = pi ? dq[i + 1] : (pprev ? d : dq[i]);
        int   ni = pi ? iq[i + 1] : (pprev ? j : iq[i]);
        dq[i] = nd;
        iq[i] = ni;
        pprev = pi;
    }
    dq[KK - 1] = pprev ? d : dq[KK - 1];
    iq[KK - 1] = pprev ? j : iq[KK - 1];
}

// W* = min of the 4 slice-worsts of this query (slices = adjacent lanes).
__device__ __forceinline__ float slice_min4(float w) {
    w = fminf(w, __shfl_xor_sync(0xffffffffu, w, 1));
    w = fminf(w, __shfl_xor_sync(0xffffffffu, w, 2));
    return w;
}

__global__ __launch_bounds__(BLOCK, 4) void knn_topk_kernel(
    const float* __restrict__ p1,
    const float* __restrict__ p2,
    float* __restrict__ out)
{
    extern __shared__ char dsm[];

    const int slice = threadIdx.x & 3;
    const int n     = blockIdx.x / BPB;
    const int qi    = (blockIdx.x % BPB) * QPB + (threadIdx.x >> 2);

    const float* p1r = p1 + ((size_t)n * P1N + qi) * 3;
    const float x1 = p1r[0], y1 = p1r[1], z1 = p1r[2];
    const float sq1 = sumsq3(x1, y1, z1);

    const unsigned long long X1p  = pack2(x1, x1);
    const unsigned long long Y1p  = pack2(y1, y1);
    const unsigned long long Z1p  = pack2(z1, z1);
    const unsigned long long SQ1p = pack2(sq1, sq1);
    const unsigned long long N2p  = pack2(-2.0f, -2.0f);

    float dq[KK];
    int   iq[KK];
    const float INF = __int_as_float(0x7f800000);
#pragma unroll
    for (int i = 0; i < KK; i++) { dq[i] = INF; iq[i] = 0; }

    const float* p2b = p2 + (size_t)n * P2N * 3;
    float wstar = INF;

#pragma unroll 1
    for (int t0 = 0; t0 < P2N; t0 += TILE) {
        __syncthreads();
        // stage pairs: [x0,x1,y0,y1 | z0,z1,q0,q1], 32B per pair
        for (int k = threadIdx.x; k < PAIRS; k += BLOCK) {
            const float2* pr2 = (const float2*)(p2b + (size_t)(t0 + 2 * k) * 3);
            float2 a = pr2[0], b = pr2[1], c = pr2[2];
            // a=(x0,y0) b=(z0,x1) c=(y1,z1)
            float q0 = sumsq3(a.x, a.y, b.x);
            float q1 = sumsq3(b.y, c.x, c.y);
            float4* dst = (float4*)dsm + 2 * k;
            dst[0] = make_float4(a.x, b.y, a.y, c.x);   // x0,x1,y0,y1
            dst[1] = make_float4(b.x, c.y, q0, q1);     // z0,z1,q0,q1
        }
        __syncthreads();

#pragma unroll 1
        for (int cc = 0; cc < NCHUNK; cc++) {
            // lane's pairs: tile pair index pi = 4*p + slice, p = cc*32+u
            const char* base = dsm + ((4 * (cc * CHUNKP) + slice) * 32);
            unsigned m0 = 0, m1 = 0;
            // FULL unroll: constant smem offsets (no IMAD) and constant
            // immediate bit masks (@p LOP3, no SHF) per candidate.
#pragma unroll
            for (int u = 0; u < CHUNKP; u++) {
                const ulonglong2* pp =
                    (const ulonglong2*)(base + (size_t)u * 128);
                ulonglong2 A = pp[0];   // (x0,x1),(y0,y1)
                ulonglong2 B = pp[1];   // (z0,z1),(q0,q1)
                float d0, d1;
                dist2(A.x, A.y, B.x, B.y, X1p, Y1p, Z1p, SQ1p, N2p, d0, d1);
                // '<=' keeps boundary ties so index resolution stays exact
                if (u < 16) {
                    m0 = (d0 <= wstar) ? (m0 | (1u << (2 * u)))     : m0;
                    m0 = (d1 <= wstar) ? (m0 | (1u << (2 * u + 1))) : m0;
                } else {
                    m1 = (d0 <= wstar) ? (m1 | (1u << (2 * u - 32))) : m1;
                    m1 = (d1 <= wstar) ? (m1 | (1u << (2 * u - 31))) : m1;
                }
            }

            // uniform drain: ascending bit order == ascending j per lane
            int cnt = __popc(m0) + __popc(m1);
            int mx  = (int)__reduce_max_sync(0xffffffffu, (unsigned)cnt);
            unsigned long long m =
                ((unsigned long long)m1 << 32) | (unsigned long long)m0;
#pragma unroll 1
            for (int k = 0; k < mx; k++) {
                bool en = (k < cnt);
                int  b  = en ? (__ffsll((long long)m) - 1) : 0;
                m &= m - 1;
                const ulonglong2* pp =
                    (const ulonglong2*)(base + (size_t)(b >> 1) * 128);
                ulonglong2 A = pp[0];
                ulonglong2 B = pp[1];
                int h = b & 1;
                float x = uhalf(A.x, h), y = uhalf(A.y, h);
                float z = uhalf(B.x, h), q = uhalf(B.y, h);
                float inr = __fmaf_rn(z1, z, __fmaf_rn(y1, y,
                             __fmul_rn(x1, x)));
                float d = __fmaf_rn(-2.0f, inr, __fadd_rn(sq1, q));
                int li = 8 * (cc * CHUNKP + (b >> 1)) + 2 * slice + h;
                ladder(en ? d : INF, t0 + li, dq, iq);
            }
            wstar = slice_min4(dq[0]);
        }
    }

    // cross-slice merge: two ONE-DIRECTIONAL rounds (R13-proven exact).
#pragma unroll
    for (int k = 0; k < KK; k++) {
        float md = __shfl_xor_sync(0xffffffffu, dq[k], 1);
        int   mj = __shfl_xor_sync(0xffffffffu, iq[k], 1);
        ladder_tie(((slice & 1) == 0) ? md : INF, mj, dq, iq);
    }
#pragma unroll
    for (int k = 0; k < KK; k++) {
        float md = __shfl_xor_sync(0xffffffffu, dq[k], 2);
        int   mj = __shfl_xor_sync(0xffffffffu, iq[k], 2);
        ladder_tie((slice == 0) ? md : INF, mj, dq, iq);
    }

    if (slice == 0) {
        const size_t base = ((size_t)n * P1N + qi) * KK;
        const size_t NPK  = (size_t)NB * P1N * KK;
#pragma unroll
        for (int k = 0; k < KK; k++) {
            out[base + k]       = (float)iq[KK - 1 - k];
            out[NPK + base + k] = dq[KK - 1 - k];
        }
    }
}

extern "C" void kernel_launch(void* const* d_in, const int* in_sizes, int n_in,
                              void* d_out, int out_size)
{
    const float* p1 = (const float*)d_in[0];
    const float* p2 = (const float*)d_in[1];
    float* out = (float*)d_out;

    static bool attr_set = false;
    if (!attr_set) {
        cudaFuncSetAttribute(knn_topk_kernel,
                             cudaFuncAttributeMaxDynamicSharedMemorySize,
                             SMEM_BYTES);
        attr_set = true;
    }

    dim3 grid(NB * BPB);
    dim3 block(BLOCK);
    knn_topk_kernel<<<grid, block, SMEM_BYTES>>>(p1, p2, out);
}

// round 17
// speedup vs baseline: 3.2078x; 1.0196x over previous
#include <cuda_runtime.h>

#define NB      4
#define P1N     8192
#define P2N     8192
#define KK      16
#define TILE    1024
#define QPB     64
#define BLOCK   256            // 4 slices per query
#define BPB     (P1N / QPB)    // 128 blocks per batch
#define PAIRS   (TILE / 2)     // 512 pairs per tile
#define CHUNKP  16             // pairs per chunk per lane (= 32 candidates)
#define NCHUNK  8              // chunks per tile per lane
#define SMEM_BYTES (PAIRS * 32)

// BIT-EXACT (proven R8): XLA small-row shuffle reduce (x^2+z^2)+y^2
__device__ __forceinline__ float sumsq3(float x, float y, float z) {
    return __fadd_rn(__fadd_rn(__fmul_rn(x, x), __fmul_rn(z, z)),
                     __fmul_rn(y, y));
}

__device__ __forceinline__ unsigned long long pack2(float a, float b) {
    unsigned long long r;
    asm("mov.b64 %0, {%1, %2};" : "=l"(r) : "f"(a), "f"(b));
    return r;
}

// packed distance for a candidate pair; per-element bit-identical to the
// scalar chain: d = fma(-2, fma(z1,z, fma(y1,y, mul(x1,x))), add(sq1,q))
__device__ __forceinline__ void dist2(
    unsigned long long xp, unsigned long long yp, unsigned long long zp,
    unsigned long long qp, unsigned long long X1, unsigned long long Y1,
    unsigned long long Z1, unsigned long long SQ1, unsigned long long N2,
    float& d0, float& d1)
{
    asm("{\n\t"
        ".reg .b64 t, s;\n\t"
        "mul.rn.f32x2 t, %2, %3;\n\t"
        "fma.rn.f32x2 t, %4, %5, t;\n\t"
        "fma.rn.f32x2 t, %6, %7, t;\n\t"
        "add.rn.f32x2 s, %8, %9;\n\t"
        "fma.rn.f32x2 t, %10, t, s;\n\t"
        "mov.b64 {%0, %1}, t;\n\t"
        "}"
        : "=f"(d0), "=f"(d1)
        : "l"(X1), "l"(xp), "l"(Y1), "l"(yp), "l"(Z1), "l"(zp),
          "l"(SQ1), "l"(qp), "l"(N2));
}

__device__ __forceinline__ float uhalf(unsigned long long u, int h) {
    return __int_as_float((int)(h ? (u >> 32) : (u & 0xffffffffu)));
}

// Exact insert into descending top-K. d==INF or d>=dq[0] -> identity.
// Strict '<' + ascending-j order => lowest index wins ties (== lex (d,j)).
__device__ __forceinline__ void ladder(float d, int j,
                                       float (&dq)[KK], int (&iq)[KK]) {
    bool pprev = d < dq[0];
#pragma unroll
    for (int i = 0; i < KK - 1; i++) {
        bool pi = d < dq[i + 1];
        float nd = pi ? dq[i + 1] : fminf(d, dq[i]);
        int   ni = pi ? iq[i + 1] : (pprev ? j : iq[i]);
        dq[i] = nd;
        iq[i] = ni;
        pprev = pi;
    }
    dq[KK - 1] = fminf(d, dq[KK - 1]);
    iq[KK - 1] = pprev ? j : iq[KK - 1];
}

// Lexicographic-(d,j) insert for cross-slice merge. d==INF -> identity.
__device__ __forceinline__ void ladder_tie(float d, int j,
                                           float (&dq)[KK], int (&iq)[KK]) {
    bool pprev = (d < dq[0]) || (d == dq[0] && j < iq[0]);
#pragma unroll
    for (int i = 0; i < KK - 1; i++) {
        bool pi = (d < dq[i + 1]) || (d == dq[i + 1] && j < iq[i + 1]);
        float nd = pi ? dq[i + 1] : (pprev ? d : dq[i]);
        int   ni = pi ? iq[i + 1] : (pprev ? j : iq[i]);
        dq[i] = nd;
        iq[i] = ni;
        pprev = pi;
    }
    dq[KK - 1] = pprev ? d : dq[KK - 1];
    iq[KK - 1] = pprev ? j : iq[KK - 1];
}

// W* = min of the 4 slice-worsts of this query (slices = adjacent lanes).
__device__ __forceinline__ float slice_min4(float w) {
    w = fminf(w, __shfl_xor_sync(0xffffffffu, w, 1));
    w = fminf(w, __shfl_xor_sync(0xffffffffu, w, 2));
    return w;
}

__global__ __launch_bounds__(BLOCK, 4) void knn_topk_kernel(
    const float* __restrict__ p1,
    const float* __restrict__ p2,
    float* __restrict__ out)
{
    extern __shared__ char dsm[];

    const int slice = threadIdx.x & 3;
    const int n     = blockIdx.x / BPB;
    const int qi    = (blockIdx.x % BPB) * QPB + (threadIdx.x >> 2);

    const float* p1r = p1 + ((size_t)n * P1N + qi) * 3;
    const float x1 = p1r[0], y1 = p1r[1], z1 = p1r[2];
    const float sq1 = sumsq3(x1, y1, z1);

    const unsigned long long X1p  = pack2(x1, x1);
    const unsigned long long Y1p  = pack2(y1, y1);
    const unsigned long long Z1p  = pack2(z1, z1);
    const unsigned long long SQ1p = pack2(sq1, sq1);
    const unsigned long long N2p  = pack2(-2.0f, -2.0f);

    float dq[KK];
    int   iq[KK];
    const float INF = __int_as_float(0x7f800000);
#pragma unroll
    for (int i = 0; i < KK; i++) { dq[i] = INF; iq[i] = 0; }

    const float* p2b = p2 + (size_t)n * P2N * 3;
    float wstar = INF;
    bool  warm  = true;

#pragma unroll 1
    for (int t0 = 0; t0 < P2N; t0 += TILE) {
        __syncthreads();
        // stage pairs: [x0,x1,y0,y1 | z0,z1,q0,q1], 32B per pair
        for (int k = threadIdx.x; k < PAIRS; k += BLOCK) {
            const float2* pr2 = (const float2*)(p2b + (size_t)(t0 + 2 * k) * 3);
            float2 a = pr2[0], b = pr2[1], c = pr2[2];
            // a=(x0,y0) b=(z0,x1) c=(y1,z1)
            float q0 = sumsq3(a.x, a.y, b.x);
            float q1 = sumsq3(b.y, c.x, c.y);
            float4* dst = (float4*)dsm + 2 * k;
            dst[0] = make_float4(a.x, b.y, a.y, c.x);   // x0,x1,y0,y1
            dst[1] = make_float4(b.x, c.y, q0, q1);     // z0,z1,q0,q1
        }
        __syncthreads();

        if (warm) {
            // tile 0, chunk 0: wstar == INF, every candidate passes —
            // run direct unconditional ladders, then seed wstar.
            warm = false;
            const char* base = dsm + (size_t)slice * 32;
#pragma unroll 1
            for (int u = 0; u < CHUNKP; u++) {
                const ulonglong2* pp =
                    (const ulonglong2*)(base + (size_t)u * 128);
                ulonglong2 A = pp[0];
                ulonglong2 B = pp[1];
                float d0, d1;
                dist2(A.x, A.y, B.x, B.y, X1p, Y1p, Z1p, SQ1p, N2p, d0, d1);
                int li = 8 * u + 2 * slice;
                ladder(d0, li, dq, iq);
                ladder(d1, li + 1, dq, iq);
            }
            wstar = slice_min4(dq[0]);
        }

#pragma unroll 1
        for (int cc = (t0 == 0) ? 1 : 0; cc < NCHUNK; cc++) {
            // lane's pairs: tile pair index pi = 4*(cc*16+u) + slice
            const char* base = dsm + ((4 * (cc * CHUNKP) + slice) * 32);
            unsigned m0 = 0;
            // small full unroll: constant smem offsets, constant immediate
            // bit masks; live set fits the 64-reg budget (no spills).
#pragma unroll
            for (int u = 0; u < CHUNKP; u++) {
                const ulonglong2* pp =
                    (const ulonglong2*)(base + (size_t)u * 128);
                ulonglong2 A = pp[0];   // (x0,x1),(y0,y1)
                ulonglong2 B = pp[1];   // (z0,z1),(q0,q1)
                float d0, d1;
                dist2(A.x, A.y, B.x, B.y, X1p, Y1p, Z1p, SQ1p, N2p, d0, d1);
                // '<=' keeps boundary ties so index resolution stays exact
                if (d0 <= wstar) m0 |= (1u << (2 * u));
                if (d1 <= wstar) m0 |= (1u << (2 * u + 1));
            }

            // uniform drain: ascending bit order == ascending j per lane
            int cnt = __popc(m0);
            int mx  = (int)__reduce_max_sync(0xffffffffu, (unsigned)cnt);
#pragma unroll 1
            for (int k = 0; k < mx; k++) {
                bool en = (k < cnt);
                int  b  = en ? (__ffs(m0) - 1) : 0;
                m0 &= m0 - 1;
                const ulonglong2* pp =
                    (const ulonglong2*)(base + (size_t)(b >> 1) * 128);
                ulonglong2 A = pp[0];
                ulonglong2 B = pp[1];
                int h = b & 1;
                float x = uhalf(A.x, h), y = uhalf(A.y, h);
                float z = uhalf(B.x, h), q = uhalf(B.y, h);
                float inr = __fmaf_rn(z1, z, __fmaf_rn(y1, y,
                             __fmul_rn(x1, x)));
                float d = __fmaf_rn(-2.0f, inr, __fadd_rn(sq1, q));
                int li = 8 * (cc * CHUNKP + (b >> 1)) + 2 * slice + h;
                ladder(en ? d : INF, t0 + li, dq, iq);
            }
            wstar = slice_min4(dq[0]);
        }
    }

    // cross-slice merge: two ONE-DIRECTIONAL rounds (R13-proven exact).
#pragma unroll
    for (int k = 0; k < KK; k++) {
        float md = __shfl_xor_sync(0xffffffffu, dq[k], 1);
        int   mj = __shfl_xor_sync(0xffffffffu, iq[k], 1);
        ladder_tie(((slice & 1) == 0) ? md : INF, mj, dq, iq);
    }
#pragma unroll
    for (int k = 0; k < KK; k++) {
        float md = __shfl_xor_sync(0xffffffffu, dq[k], 2);
        int   mj = __shfl_xor_sync(0xffffffffu, iq[k], 2);
        ladder_tie((slice == 0) ? md : INF, mj, dq, iq);
    }

    if (slice == 0) {
        const size_t base = ((size_t)n * P1N + qi) * KK;
        const size_t NPK  = (size_t)NB * P1N * KK;
#pragma unroll
        for (int k = 0; k < KK; k++) {
            out[base + k]       = (float)iq[KK - 1 - k];
            out[NPK + base + k] = dq[KK - 1 - k];
        }
    }
}

extern "C" void kernel_launch(void* const* d_in, const int* in_sizes, int n_in,
                              void* d_out, int out_size)
{
    const float* p1 = (const float*)d_in[0];
    const float* p2 = (const float*)d_in[1];
    float* out = (float*)d_out;

    static bool attr_set = false;
    if (!attr_set) {
        cudaFuncSetAttribute(knn_topk_kernel,
                             cudaFuncAttributeMaxDynamicSharedMemorySize,
                             SMEM_BYTES);
        attr_set = true;
    }

    dim3 grid(NB * BPB);
    dim3 block(BLOCK);
    knn_topk_kernel<<<grid, block, SMEM_BYTES>>>(p1, p2, out);
}